// round 1
// baseline (speedup 1.0000x reference)
#include <cuda_runtime.h>
#include <math.h>

#define B   64
#define T   4096
#define QS  1024
#define KS  1024

// Scratch (no allocations allowed)
__device__ float g_mids[B * KS];      // 256 KB
__device__ float g_scores[B * T];     // 1 MB

// ---------------------------------------------------------------------------
// Kernel 1: mids[b,k] = sum_q W[k,q] * query[b,q]
// C[64,1024] = A[64,1024] (query) x B[1024,1024] (W, row=k, col=q), both q-major.
// One block computes the full b-range (64) x 64 k-columns. grid = KS/64 = 16.
// 256 threads, each computes a 4x4 micro-tile. K-chunk = 32.
// ---------------------------------------------------------------------------
#define KC 32
__global__ void mids_kernel(const float* __restrict__ query,
                            const float* __restrict__ W) {
    __shared__ float sA[64][KC + 1];   // query tile  [b][q]
    __shared__ float sB[64][KC + 1];   // W tile      [k][q]

    const int k0  = blockIdx.x * 64;
    const int tid = threadIdx.x;          // 0..255
    const int tx  = tid & 15;             // k micro-tile index
    const int ty  = tid >> 4;             // b micro-tile index

    float acc[4][4];
#pragma unroll
    for (int i = 0; i < 4; i++)
#pragma unroll
        for (int j = 0; j < 4; j++) acc[i][j] = 0.f;

    for (int q0 = 0; q0 < QS; q0 += KC) {
        // load 64x32 tiles (2048 elems, 8 per thread)
#pragma unroll
        for (int s = 0; s < 8; s++) {
            int idx = tid + s * 256;
            int r = idx >> 5;     // /32
            int c = idx & 31;
            sA[r][c] = query[r * QS + q0 + c];
            sB[r][c] = W[(size_t)(k0 + r) * QS + q0 + c];
        }
        __syncthreads();

#pragma unroll
        for (int qq = 0; qq < KC; qq++) {
            float a[4], bb[4];
#pragma unroll
            for (int i = 0; i < 4; i++) a[i]  = sA[ty * 4 + i][qq];
#pragma unroll
            for (int j = 0; j < 4; j++) bb[j] = sB[tx * 4 + j][qq];
#pragma unroll
            for (int i = 0; i < 4; i++)
#pragma unroll
                for (int j = 0; j < 4; j++) acc[i][j] += a[i] * bb[j];
        }
        __syncthreads();
    }

#pragma unroll
    for (int i = 0; i < 4; i++) {
        int b = ty * 4 + i;
#pragma unroll
        for (int j = 0; j < 4; j++) {
            int k = k0 + tx * 4 + j;
            g_mids[b * KS + k] = acc[i][j];
        }
    }
}

// ---------------------------------------------------------------------------
// Kernel 2: scores[b,t] = tanh(key[b,t,:] . mids[b,:] + bias)
// block = (b, 32-row t chunk). 256 threads = 8 warps; warp per row (4 rows/warp).
// mids[b] cached in smem. 8 independent float4 loads per lane -> MLP 8.
// ---------------------------------------------------------------------------
#define T_PER_BLOCK 32
__global__ void scores_kernel(const float* __restrict__ key,
                              const float* __restrict__ bias) {
    __shared__ float s_mids[KS];
    const int b = blockIdx.y;

    for (int i = threadIdx.x; i < KS; i += blockDim.x)
        s_mids[i] = g_mids[b * KS + i];
    __syncthreads();

    const float bias0 = bias[0];
    const int warp = threadIdx.x >> 5;
    const int lane = threadIdx.x & 31;
    const int t0   = blockIdx.x * T_PER_BLOCK;
    const float4* smv = (const float4*)s_mids;

#pragma unroll
    for (int ti = warp; ti < T_PER_BLOCK; ti += 8) {
        const int t = t0 + ti;
        const float4* row =
            (const float4*)(key + ((size_t)b * T + t) * (size_t)KS);
        float acc = 0.f;
#pragma unroll
        for (int i = 0; i < 8; i++) {
            float4 kv = row[lane + i * 32];
            float4 mv = smv[lane + i * 32];
            acc += kv.x * mv.x + kv.y * mv.y + kv.z * mv.z + kv.w * mv.w;
        }
#pragma unroll
        for (int o = 16; o > 0; o >>= 1)
            acc += __shfl_xor_sync(0xffffffffu, acc, o);
        if (lane == 0)
            g_scores[b * T + t] = tanhf(acc + bias0);
    }
}

// ---------------------------------------------------------------------------
// Kernel 3: masked softmax over t. One block (1024 thr) per b, 4 elems/thread.
// ---------------------------------------------------------------------------
__global__ void softmax_kernel(const float* __restrict__ mask,
                               float* __restrict__ out) {
    const int b   = blockIdx.x;
    const int tid = threadIdx.x;           // 0..1023
    __shared__ float red[32];

    float v[4], m[4];
#pragma unroll
    for (int i = 0; i < 4; i++) {
        int t = tid + i * 1024;
        v[i] = g_scores[b * T + t];
        m[i] = mask[b * T + t];
    }

    // --- block max ---
    float mx = fmaxf(fmaxf(v[0], v[1]), fmaxf(v[2], v[3]));
#pragma unroll
    for (int o = 16; o > 0; o >>= 1)
        mx = fmaxf(mx, __shfl_xor_sync(0xffffffffu, mx, o));
    if ((tid & 31) == 0) red[tid >> 5] = mx;
    __syncthreads();
    if (tid < 32) {
        float x = red[tid];
#pragma unroll
        for (int o = 16; o > 0; o >>= 1)
            x = fmaxf(x, __shfl_xor_sync(0xffffffffu, x, o));
        red[tid] = x;
    }
    __syncthreads();
    mx = red[0];
    __syncthreads();

    // --- exp * mask, block sum ---
    float s = 0.f;
#pragma unroll
    for (int i = 0; i < 4; i++) {
        v[i] = __expf(v[i] - mx) * m[i];
        s += v[i];
    }
#pragma unroll
    for (int o = 16; o > 0; o >>= 1)
        s += __shfl_xor_sync(0xffffffffu, s, o);
    if ((tid & 31) == 0) red[tid >> 5] = s;
    __syncthreads();
    if (tid < 32) {
        float x = red[tid];
#pragma unroll
        for (int o = 16; o > 0; o >>= 1)
            x += __shfl_xor_sync(0xffffffffu, x, o);
        red[tid] = x;
    }
    __syncthreads();
    const float inv = 1.0f / red[0];

#pragma unroll
    for (int i = 0; i < 4; i++) {
        int t = tid + i * 1024;
        out[b * T + t] = v[i] * inv;
    }
}

extern "C" void kernel_launch(void* const* d_in, const int* in_sizes, int n_in,
                              void* d_out, int out_size) {
    const float* query = (const float*)d_in[0];   // [B, QS]
    const float* key   = (const float*)d_in[1];   // [B, T, KS]
    const float* mask  = (const float*)d_in[2];   // [B, T]
    const float* W     = (const float*)d_in[3];   // [KS, QS]
    const float* bias  = (const float*)d_in[4];   // [1]
    float* out = (float*)d_out;                   // [B, T]

    mids_kernel<<<KS / 64, 256>>>(query, W);

    dim3 grid2(T / T_PER_BLOCK, B);
    scores_kernel<<<grid2, 256>>>(key, bias);

    softmax_kernel<<<B, 1024>>>(mask, out);
}

// round 2
// speedup vs baseline: 1.2689x; 1.2689x over previous
#include <cuda_runtime.h>
#include <math.h>

#define B   64
#define T   4096
#define QS  1024
#define KS  1024
#define QSPLIT 16           // q-chunks for split-K mids
#define QCHUNK (QS / QSPLIT)  // 64

// Scratch (no allocations allowed)
__device__ float g_mids[B * KS];               // 256 KB
__device__ float g_part[QSPLIT * B * KS];      // 4 MB split-K partials
__device__ float g_scores[B * T];              // 1 MB

// ---------------------------------------------------------------------------
// Kernel 1a: split-K partial GEMM.
// Block (kx, qc): 64 b x 64 k outputs, summed over q in [qc*64, qc*64+64).
// 256 threads, 4x4 micro-tile per thread. Deterministic (no atomics).
// ---------------------------------------------------------------------------
#define KC 32
__global__ void mids_partial_kernel(const float* __restrict__ query,
                                    const float* __restrict__ W) {
    __shared__ float sA[64][KC + 1];   // query tile  [b][q]
    __shared__ float sB[64][KC + 1];   // W tile      [k][q]

    const int k0  = blockIdx.x * 64;
    const int qc  = blockIdx.y;
    const int tid = threadIdx.x;          // 0..255
    const int tx  = tid & 15;             // k micro-tile index
    const int ty  = tid >> 4;             // b micro-tile index

    float acc[4][4];
#pragma unroll
    for (int i = 0; i < 4; i++)
#pragma unroll
        for (int j = 0; j < 4; j++) acc[i][j] = 0.f;

    const int qbase = qc * QCHUNK;
    for (int q0 = qbase; q0 < qbase + QCHUNK; q0 += KC) {
        // load 64x32 tiles (2048 elems, 8 per thread)
#pragma unroll
        for (int s = 0; s < 8; s++) {
            int idx = tid + s * 256;
            int r = idx >> 5;     // /32
            int c = idx & 31;
            sA[r][c] = query[r * QS + q0 + c];
            sB[r][c] = W[(size_t)(k0 + r) * QS + q0 + c];
        }
        __syncthreads();

#pragma unroll
        for (int qq = 0; qq < KC; qq++) {
            float a[4], bb[4];
#pragma unroll
            for (int i = 0; i < 4; i++) a[i]  = sA[ty * 4 + i][qq];
#pragma unroll
            for (int j = 0; j < 4; j++) bb[j] = sB[tx * 4 + j][qq];
#pragma unroll
            for (int i = 0; i < 4; i++)
#pragma unroll
                for (int j = 0; j < 4; j++) acc[i][j] += a[i] * bb[j];
        }
        __syncthreads();
    }

    float* dst = g_part + (size_t)qc * (B * KS);
#pragma unroll
    for (int i = 0; i < 4; i++) {
        int b = ty * 4 + i;
#pragma unroll
        for (int j = 0; j < 4; j++) {
            int k = k0 + tx * 4 + j;
            dst[b * KS + k] = acc[i][j];
        }
    }
}

// ---------------------------------------------------------------------------
// Kernel 1b: reduce the QSPLIT partials into g_mids (float4 vectorized).
// ---------------------------------------------------------------------------
__global__ void mids_reduce_kernel() {
    const int i = blockIdx.x * blockDim.x + threadIdx.x;  // 0 .. B*KS/4-1
    const float4* p = (const float4*)g_part;
    float4 s = p[i];
#pragma unroll
    for (int qc = 1; qc < QSPLIT; qc++) {
        float4 v = p[(size_t)qc * (B * KS / 4) + i];
        s.x += v.x; s.y += v.y; s.z += v.z; s.w += v.w;
    }
    ((float4*)g_mids)[i] = s;
}

// ---------------------------------------------------------------------------
// Kernel 2: scores[b,t] = tanh(key[b,t,:] . mids[b,:] + bias)
// block = (b, 32-row t chunk). 256 threads = 8 warps; 4 rows/warp.
// mids[b] cached in smem. 8 independent float4 loads per lane per row.
// ---------------------------------------------------------------------------
#define T_PER_BLOCK 32
__global__ void scores_kernel(const float* __restrict__ key,
                              const float* __restrict__ bias) {
    __shared__ float s_mids[KS];
    const int b = blockIdx.y;

    for (int i = threadIdx.x; i < KS; i += blockDim.x)
        s_mids[i] = g_mids[b * KS + i];
    __syncthreads();

    const float bias0 = bias[0];
    const int warp = threadIdx.x >> 5;
    const int lane = threadIdx.x & 31;
    const int t0   = blockIdx.x * T_PER_BLOCK;
    const float4* smv = (const float4*)s_mids;

#pragma unroll
    for (int ti = warp; ti < T_PER_BLOCK; ti += 8) {
        const int t = t0 + ti;
        const float4* row =
            (const float4*)(key + ((size_t)b * T + t) * (size_t)KS);
        float acc = 0.f;
#pragma unroll
        for (int i = 0; i < 8; i++) {
            float4 kv = row[lane + i * 32];
            float4 mv = smv[lane + i * 32];
            acc += kv.x * mv.x + kv.y * mv.y + kv.z * mv.z + kv.w * mv.w;
        }
#pragma unroll
        for (int o = 16; o > 0; o >>= 1)
            acc += __shfl_xor_sync(0xffffffffu, acc, o);
        if (lane == 0)
            g_scores[b * T + t] = tanhf(acc + bias0);
    }
}

// ---------------------------------------------------------------------------
// Kernel 3: masked softmax over t. One block (1024 thr) per b, 4 elems/thread.
// ---------------------------------------------------------------------------
__global__ void softmax_kernel(const float* __restrict__ mask,
                               float* __restrict__ out) {
    const int b   = blockIdx.x;
    const int tid = threadIdx.x;           // 0..1023
    __shared__ float red[32];

    float v[4], m[4];
#pragma unroll
    for (int i = 0; i < 4; i++) {
        int t = tid + i * 1024;
        v[i] = g_scores[b * T + t];
        m[i] = mask[b * T + t];
    }

    // --- block max ---
    float mx = fmaxf(fmaxf(v[0], v[1]), fmaxf(v[2], v[3]));
#pragma unroll
    for (int o = 16; o > 0; o >>= 1)
        mx = fmaxf(mx, __shfl_xor_sync(0xffffffffu, mx, o));
    if ((tid & 31) == 0) red[tid >> 5] = mx;
    __syncthreads();
    if (tid < 32) {
        float x = red[tid];
#pragma unroll
        for (int o = 16; o > 0; o >>= 1)
            x = fmaxf(x, __shfl_xor_sync(0xffffffffu, x, o));
        red[tid] = x;
    }
    __syncthreads();
    mx = red[0];
    __syncthreads();

    // --- exp * mask, block sum ---
    float s = 0.f;
#pragma unroll
    for (int i = 0; i < 4; i++) {
        v[i] = __expf(v[i] - mx) * m[i];
        s += v[i];
    }
#pragma unroll
    for (int o = 16; o > 0; o >>= 1)
        s += __shfl_xor_sync(0xffffffffu, s, o);
    if ((tid & 31) == 0) red[tid >> 5] = s;
    __syncthreads();
    if (tid < 32) {
        float x = red[tid];
#pragma unroll
        for (int o = 16; o > 0; o >>= 1)
            x += __shfl_xor_sync(0xffffffffu, x, o);
        red[tid] = x;
    }
    __syncthreads();
    const float inv = 1.0f / red[0];

#pragma unroll
    for (int i = 0; i < 4; i++) {
        int t = tid + i * 1024;
        out[b * T + t] = v[i] * inv;
    }
}

extern "C" void kernel_launch(void* const* d_in, const int* in_sizes, int n_in,
                              void* d_out, int out_size) {
    const float* query = (const float*)d_in[0];   // [B, QS]
    const float* key   = (const float*)d_in[1];   // [B, T, KS]
    const float* mask  = (const float*)d_in[2];   // [B, T]
    const float* W     = (const float*)d_in[3];   // [KS, QS]
    const float* bias  = (const float*)d_in[4];   // [1]
    float* out = (float*)d_out;                   // [B, T]

    dim3 grid1(KS / 64, QSPLIT);
    mids_partial_kernel<<<grid1, 256>>>(query, W);
    mids_reduce_kernel<<<(B * KS / 4) / 256, 256>>>();

    dim3 grid2(T / T_PER_BLOCK, B);
    scores_kernel<<<grid2, 256>>>(key, bias);

    softmax_kernel<<<B, 1024>>>(mask, out);
}

// round 3
// speedup vs baseline: 1.2967x; 1.0219x over previous
#include <cuda_runtime.h>
#include <math.h>

#define B   64
#define T   4096
#define QS  1024
#define KS  1024
#define QSPLIT 16             // q-chunks for split-K mids
#define QCHUNK (QS / QSPLIT)  // 64
#define T_PER_BLOCK 32
#define NBLK (T / T_PER_BLOCK)   // 128 t-blocks per batch row

// Scratch (no allocations allowed)
__device__ float g_mids[B * KS];               // 256 KB
__device__ float g_part[QSPLIT * B * KS];      // 4 MB split-K partials
__device__ float g_scores[B * T];              // 1 MB (holds exp(tanh)·mask)
__device__ float g_psum[B * NBLK];             // 32 KB per-block partial sums

// ---------------------------------------------------------------------------
// Kernel 1a: split-K partial GEMM for mids.
// ---------------------------------------------------------------------------
#define KC 32
__global__ void mids_partial_kernel(const float* __restrict__ query,
                                    const float* __restrict__ W) {
    __shared__ float sA[64][KC + 1];   // query tile  [b][q]
    __shared__ float sB[64][KC + 1];   // W tile      [k][q]

    const int k0  = blockIdx.x * 64;
    const int qc  = blockIdx.y;
    const int tid = threadIdx.x;          // 0..255
    const int tx  = tid & 15;
    const int ty  = tid >> 4;

    float acc[4][4];
#pragma unroll
    for (int i = 0; i < 4; i++)
#pragma unroll
        for (int j = 0; j < 4; j++) acc[i][j] = 0.f;

    const int qbase = qc * QCHUNK;
    for (int q0 = qbase; q0 < qbase + QCHUNK; q0 += KC) {
#pragma unroll
        for (int s = 0; s < 8; s++) {
            int idx = tid + s * 256;
            int r = idx >> 5;
            int c = idx & 31;
            sA[r][c] = query[r * QS + q0 + c];
            sB[r][c] = W[(size_t)(k0 + r) * QS + q0 + c];
        }
        __syncthreads();

#pragma unroll
        for (int qq = 0; qq < KC; qq++) {
            float a[4], bb[4];
#pragma unroll
            for (int i = 0; i < 4; i++) a[i]  = sA[ty * 4 + i][qq];
#pragma unroll
            for (int j = 0; j < 4; j++) bb[j] = sB[tx * 4 + j][qq];
#pragma unroll
            for (int i = 0; i < 4; i++)
#pragma unroll
                for (int j = 0; j < 4; j++) acc[i][j] += a[i] * bb[j];
        }
        __syncthreads();
    }

    float* dst = g_part + (size_t)qc * (B * KS);
#pragma unroll
    for (int i = 0; i < 4; i++) {
        int b = ty * 4 + i;
#pragma unroll
        for (int j = 0; j < 4; j++) {
            int k = k0 + tx * 4 + j;
            dst[b * KS + k] = acc[i][j];
        }
    }
}

// ---------------------------------------------------------------------------
// Kernel 1b: reduce split-K partials into g_mids.
// ---------------------------------------------------------------------------
__global__ void mids_reduce_kernel() {
    const int i = blockIdx.x * blockDim.x + threadIdx.x;
    const float4* p = (const float4*)g_part;
    float4 s = p[i];
#pragma unroll
    for (int qc = 1; qc < QSPLIT; qc++) {
        float4 v = p[(size_t)qc * (B * KS / 4) + i];
        s.x += v.x; s.y += v.y; s.z += v.z; s.w += v.w;
    }
    ((float4*)g_mids)[i] = s;
}

// ---------------------------------------------------------------------------
// Kernel 2: e[b,t] = exp(tanh(key[b,t,:] . mids[b,:] + bias)) * mask[b,t]
// plus per-block partial sum of e (deterministic tree, no atomics).
// tanh bounds scores to [-1,1], so skipping the max-subtraction is safe:
// the final normalization makes the result algebraically identical.
// ---------------------------------------------------------------------------
__global__ void scores_kernel(const float* __restrict__ key,
                              const float* __restrict__ mask,
                              const float* __restrict__ bias) {
    __shared__ float s_mids[KS];
    __shared__ float s_wsum[8];
    const int b = blockIdx.y;

    for (int i = threadIdx.x; i < KS; i += blockDim.x)
        s_mids[i] = g_mids[b * KS + i];
    __syncthreads();

    const float bias0 = bias[0];
    const int warp = threadIdx.x >> 5;
    const int lane = threadIdx.x & 31;
    const int t0   = blockIdx.x * T_PER_BLOCK;
    const float4* smv = (const float4*)s_mids;

    float wsum = 0.f;   // lane-0 accumulator of this warp's e values

#pragma unroll
    for (int ti = warp; ti < T_PER_BLOCK; ti += 8) {
        const int t = t0 + ti;
        const float4* row =
            (const float4*)(key + ((size_t)b * T + t) * (size_t)KS);
        float acc = 0.f;
#pragma unroll
        for (int i = 0; i < 8; i++) {
            float4 kv = __ldcs(row + lane + i * 32);   // streaming: evict-first
            float4 mv = smv[lane + i * 32];
            acc += kv.x * mv.x + kv.y * mv.y + kv.z * mv.z + kv.w * mv.w;
        }
#pragma unroll
        for (int o = 16; o > 0; o >>= 1)
            acc += __shfl_xor_sync(0xffffffffu, acc, o);
        if (lane == 0) {
            float e = __expf(tanhf(acc + bias0)) * mask[b * T + t];
            g_scores[b * T + t] = e;
            wsum += e;
        }
    }

    if (lane == 0) s_wsum[warp] = wsum;
    __syncthreads();
    if (threadIdx.x == 0) {
        float s = 0.f;
#pragma unroll
        for (int w = 0; w < 8; w++) s += s_wsum[w];
        g_psum[b * NBLK + blockIdx.x] = s;
    }
}

// ---------------------------------------------------------------------------
// Kernel 3: per-b sum of partials, then normalize. One block (1024 thr) per b.
// ---------------------------------------------------------------------------
__global__ void normalize_kernel(float* __restrict__ out) {
    const int b   = blockIdx.x;
    const int tid = threadIdx.x;           // 0..1023
    __shared__ float red[4];
    __shared__ float s_inv;

    // reduce the 128 per-block partials (threads 0..127)
    if (tid < 128) {
        float s = g_psum[b * NBLK + tid];
#pragma unroll
        for (int o = 16; o > 0; o >>= 1)
            s += __shfl_xor_sync(0xffffffffu, s, o);
        if ((tid & 31) == 0) red[tid >> 5] = s;
    }
    __syncthreads();
    if (tid == 0)
        s_inv = 1.0f / (red[0] + red[1] + red[2] + red[3]);
    __syncthreads();
    const float inv = s_inv;

    const float4* src = (const float4*)(g_scores + b * T);
    float4* dst = (float4*)(out + b * T);
    float4 v = src[tid];
    v.x *= inv; v.y *= inv; v.z *= inv; v.w *= inv;
    dst[tid] = v;
}

extern "C" void kernel_launch(void* const* d_in, const int* in_sizes, int n_in,
                              void* d_out, int out_size) {
    const float* query = (const float*)d_in[0];   // [B, QS]
    const float* key   = (const float*)d_in[1];   // [B, T, KS]
    const float* mask  = (const float*)d_in[2];   // [B, T]
    const float* W     = (const float*)d_in[3];   // [KS, QS]
    const float* bias  = (const float*)d_in[4];   // [1]
    float* out = (float*)d_out;                   // [B, T]

    dim3 grid1(KS / 64, QSPLIT);
    mids_partial_kernel<<<grid1, 256>>>(query, W);
    mids_reduce_kernel<<<(B * KS / 4) / 256, 256>>>();

    dim3 grid2(NBLK, B);
    scores_kernel<<<grid2, 256>>>(key, mask, bias);

    normalize_kernel<<<B, 1024>>>(out);
}